// round 5
// baseline (speedup 1.0000x reference)
#include <cuda_runtime.h>
#include <math.h>

// ---------------------------------------------------------------------------
// Fully-fused persistent kernel (single launch, software grid barriers).
//
// loss = sum_i event_i*(log(denom_i) - xbeta0_i) + n*lv0
//      + clip(exp(-lv1),0,1) * cost2 + lv1
// order   = stable descending sort by time (ties: lower original index first)
// denom_i = cumsum(exp(xbeta0[order]))[i]
// cost2   = M(M+1)/2 - sum_ii exp(-xh_ii) * cumsum(exp(xh))[ii]
//
// Sort: time uniform in [0,1000) -> 2^18 value buckets numbered in DESCENDING
// time order; counting sort + per-bucket insertion sort on the 50-bit
// composite key (deterministic, top_k-stable).
//
// Residency: GRID=148 blocks of 1024 threads <= SM count => all CTAs
// co-resident => atomic spin grid-barrier is safe.
// g_hist is zero at entry: zero-initialized at load, re-zeroed during the
// scatter phase of every run (invariant across graph replays).
// ---------------------------------------------------------------------------

#define MAXN (1 << 19)
#define NB   (1 << 18)
#define MAXM 16384
#define GRID 148
#define BLK  1024

__device__ unsigned long long g_keys[MAXN];
__device__ int    g_hist[NB];        // zero at kernel entry (see invariant above)
__device__ int    g_off[NB];
__device__ int    g_off_mut[NB];
__device__ int    g_scanBlk[GRID];
__device__ float2 g_sx[MAXN];
__device__ double g_coxBlk[GRID];
__device__ double g_blockAcc[GRID];
__device__ float  g_xh_glob[MAXM];   // fallback if m > 8192
__device__ unsigned g_bar_gen = 0;   // monotone across replays (ok)
__device__ unsigned g_bar_cnt = 0;   // returns to 0 after every barrier

__device__ __forceinline__ void grid_bar() {
    __syncthreads();
    if (threadIdx.x == 0) {
        unsigned gen = atomicAdd(&g_bar_gen, 0u);
        __threadfence();                       // release my writes
        unsigned arrived = atomicAdd(&g_bar_cnt, 1u);
        if (arrived == GRID - 1) {
            g_bar_cnt = 0;
            __threadfence();
            atomicAdd(&g_bar_gen, 1u);         // release everyone
        } else {
            while (atomicAdd(&g_bar_gen, 0u) == gen) __nanosleep(64);
        }
        __threadfence();                       // acquire
    }
    __syncthreads();
}

__device__ __forceinline__ int bucket_desc(float t) {
    int b = (int)(t * ((float)NB / 1000.0f));
    if (b < 0) b = 0;
    if (b > NB - 1) b = NB - 1;
    return (NB - 1) - b;
}

__global__ __launch_bounds__(BLK, 1)
void fused_kernel(const float* __restrict__ yt0, const float* __restrict__ yp0,
                  const float* __restrict__ yp1, const int* __restrict__ Hj,
                  const float* __restrict__ lv, float* __restrict__ out,
                  int n, int m, int idx_bits, unsigned idx_mask,
                  int CH_N, int CH_B) {
    __shared__ int    sh_i[BLK];
    __shared__ double sh_d[BLK];
    __shared__ float  sh_xh[8192];

    const int b = blockIdx.x, t = threadIdx.x;
    const long baseN = (long)b * CH_N;          // element-space chunk
    const long baseB = (long)b * CH_B;          // bucket-space chunk
    const long endN  = (baseN + CH_N < n)  ? baseN + CH_N : n;
    const long endB  = (baseB + CH_B < NB) ? baseB + CH_B : NB;

    // ---- P1: histogram (g_hist is zero at entry) ----
    for (long i = baseN + t; i < endN; i += BLK)
        atomicAdd(&g_hist[bucket_desc(yt0[2 * i])], 1);
    grid_bar();

    // ---- P2: per-block bucket-count sums ----
    {
        int s = 0;
        for (long i = baseB + t; i < endB; i += BLK) s += g_hist[i];
        sh_i[t] = s; __syncthreads();
        for (int off = BLK / 2; off > 0; off >>= 1) {
            if (t < off) sh_i[t] += sh_i[t + off];
            __syncthreads();
        }
        if (t == 0) g_scanBlk[b] = sh_i[0];
    }
    grid_bar();

    // ---- P3: exclusive scan -> bucket offsets ----
    {
        int v = (t < b) ? g_scanBlk[t] : 0;
        sh_i[t] = v; __syncthreads();
        for (int off = BLK / 2; off > 0; off >>= 1) {
            if (t < off) sh_i[t] += sh_i[t + off];
            __syncthreads();
        }
        int base_val = sh_i[0];
        __syncthreads();

        long i0 = baseB + (long)t * 2;
        int l0 = (i0     < endB) ? g_hist[i0]     : 0;
        int l1 = (i0 + 1 < endB) ? g_hist[i0 + 1] : 0;
        int s = l0 + l1;
        sh_i[t] = s; __syncthreads();
        for (int off = 1; off < BLK; off <<= 1) {
            int u = (t >= off) ? sh_i[t - off] : 0;
            __syncthreads();
            sh_i[t] += u;
            __syncthreads();
        }
        int run = base_val + sh_i[t] - s;
        if (i0 < endB)     { g_off[i0] = run;     g_off_mut[i0] = run;     run += l0; }
        if (i0 + 1 < endB) { g_off[i0 + 1] = run; g_off_mut[i0 + 1] = run; }
    }
    grid_bar();

    // ---- P4: scatter keys into bucket slots; re-zero hist chunk ----
    for (long i = baseN + t; i < endN; i += BLK) {
        float tv = yt0[2 * i];
        unsigned u = __float_as_uint(tv);
        u = (u & 0x80000000u) ? ~u : (u | 0x80000000u);
        unsigned long long key = ((unsigned long long)u << idx_bits) |
                                 (unsigned long long)(idx_mask - (unsigned)i);
        int bu = bucket_desc(tv);
        int pos = atomicAdd(&g_off_mut[bu], 1);
        g_keys[pos] = key;
    }
    for (long i = baseB + t; i < endB; i += BLK) g_hist[i] = 0;
    grid_bar();

    // ---- P5: per-bucket insertion sort (descending composite key) ----
    for (long bu = baseB + t; bu < endB; bu += BLK) {
        int s = g_off[bu], e = g_off_mut[bu];
        for (int i = s + 1; i < e; i++) {
            unsigned long long k = g_keys[i];
            int j = i - 1;
            while (j >= s && g_keys[j] < k) { g_keys[j + 1] = g_keys[j]; j--; }
            g_keys[j + 1] = k;
        }
    }
    grid_bar();

    // ---- P6: gather (xbeta0, event) in sorted order; block exp sums ----
    {
        double s = 0.0;
        for (long i = baseN + t; i < endN; i += BLK) {
            unsigned long long k = g_keys[i];
            unsigned orig = idx_mask - (unsigned)(k & idx_mask);
            float xb = yp0[orig];
            float ev = yt0[2 * orig + 1];
            g_sx[i] = make_float2(xb, ev);
            s += (double)expf(xb);
        }
        sh_d[t] = s; __syncthreads();
        for (int off = BLK / 2; off > 0; off >>= 1) {
            if (t < off) sh_d[t] += sh_d[t + off];
            __syncthreads();
        }
        if (t == 0) g_coxBlk[b] = sh_d[0];
    }
    grid_bar();

    // ---- P7: Cox prefix + loss ----
    {
        double v = (t < b) ? g_coxBlk[t] : 0.0;
        sh_d[t] = v; __syncthreads();
        for (int off = BLK / 2; off > 0; off >>= 1) {
            if (t < off) sh_d[t] += sh_d[t + off];
            __syncthreads();
        }
        double base_val = sh_d[0];
        __syncthreads();

        long i0 = baseN + (long)t * 2;
        float2 v0 = (i0     < endN) ? g_sx[i0]     : make_float2(0.f, 0.f);
        float2 v1 = (i0 + 1 < endN) ? g_sx[i0 + 1] : make_float2(0.f, 0.f);
        double e0 = (i0     < endN) ? (double)expf(v0.x) : 0.0;
        double e1 = (i0 + 1 < endN) ? (double)expf(v1.x) : 0.0;
        double s = e0 + e1;
        sh_d[t] = s; __syncthreads();
        for (int off = 1; off < BLK; off <<= 1) {
            double u = (t >= off) ? sh_d[t - off] : 0.0;
            __syncthreads();
            sh_d[t] += u;
            __syncthreads();
        }
        double run = base_val + sh_d[t] - s;
        double acc = 0.0;
        if (i0 < endN) {
            run += e0;
            if (v0.y != 0.0f) acc += (double)logf((float)run) - (double)v0.x;
        }
        if (i0 + 1 < endN) {
            run += e1;
            if (v1.y != 0.0f) acc += (double)logf((float)run) - (double)v1.x;
        }
        __syncthreads();
        sh_d[t] = acc; __syncthreads();
        for (int off = BLK / 2; off > 0; off >>= 1) {
            if (t < off) sh_d[t] += sh_d[t + off];
            __syncthreads();
        }
        if (t == 0) g_blockAcc[b] = sh_d[0];
    }
    grid_bar();

    // ---- P8: ordinal loss (O(M) prefix identity) + final combine (block 0) ----
    if (b == 0) {
        float* xh = (m <= 8192) ? sh_xh : g_xh_glob;
        int S = (m + BLK - 1) / BLK;
        double tot = 0.0;
        for (int k2 = 0; k2 < S; k2++) {
            int j = t * S + k2;
            if (j < m) {
                int pos = Hj[j];
                unsigned long long key = g_keys[pos];
                unsigned orig = idx_mask - (unsigned)(key & idx_mask);
                float x = yp1[orig];
                xh[j] = x;
                tot += exp((double)x);
            }
        }
        sh_d[t] = tot; __syncthreads();
        for (int off = 1; off < BLK; off <<= 1) {
            double u = (t >= off) ? sh_d[t - off] : 0.0;
            __syncthreads();
            sh_d[t] += u;
            __syncthreads();
        }
        double run = sh_d[t] - tot;
        double acc = 0.0;
        for (int k2 = 0; k2 < S; k2++) {
            int j = t * S + k2;
            if (j < m) {
                double exv = exp((double)xh[j]);
                run += exv;
                acc += run / exv;
            }
        }
        __syncthreads();
        sh_d[t] = acc; __syncthreads();
        for (int off = BLK / 2; off > 0; off >>= 1) {
            if (t < off) sh_d[t] += sh_d[t + off];
            __syncthreads();
        }
        double cost2 = 0.5 * (double)m * ((double)m + 1.0) - sh_d[0];
        __syncthreads();

        double s2 = 0.0;
        for (int k2 = t; k2 < GRID; k2 += BLK) s2 += g_blockAcc[k2];
        sh_d[t] = s2; __syncthreads();
        for (int off = BLK / 2; off > 0; off >>= 1) {
            if (t < off) sh_d[t] += sh_d[t + off];
            __syncthreads();
        }
        if (t == 0) {
            double lv0 = (double)lv[0];
            double lv1 = (double)lv[1];
            double p1 = exp(-lv1);
            if (p1 > 1.0) p1 = 1.0;
            if (p1 < 0.0) p1 = 0.0;
            out[0] = (float)((sh_d[0] + (double)n * lv0) + (p1 * cost2 + lv1));
        }
    }
}

extern "C" void kernel_launch(void* const* d_in, const int* in_sizes, int n_in,
                              void* d_out, int out_size) {
    const float* yt0      = (const float*)d_in[0];   // [N,2] (time, event)
    const float* yp0      = (const float*)d_in[2];   // [N,1] xbeta head 0
    const float* yp1      = (const float*)d_in[3];   // [N,1] xbeta head 1
    const int*   Hj       = (const int*)d_in[4];     // [M]
    const float* log_vars = (const float*)d_in[5];   // [2]

    int n = in_sizes[0] / 2;
    int m = in_sizes[4];

    int idx_bits = 0;
    while ((1u << idx_bits) < (unsigned)n) idx_bits++;
    unsigned idx_mask = (1u << idx_bits) - 1u;

    int CH_N = (n + GRID - 1) / GRID;
    int CH_B = (NB + GRID - 1) / GRID;

    fused_kernel<<<GRID, BLK>>>(yt0, yp0, yp1, Hj, log_vars, (float*)d_out,
                                n, m, idx_bits, idx_mask, CH_N, CH_B);
}

// round 6
// speedup vs baseline: 1.0058x; 1.0058x over previous
#include <cuda_runtime.h>
#include <math.h>

// ---------------------------------------------------------------------------
// Fully-fused persistent kernel, single launch, acquire-load grid barriers.
//
// loss = sum_i event_i*(log(denom_i) - xbeta0_i) + n*lv0
//      + clip(exp(-lv1),0,1) * cost2 + lv1
// order   = stable descending sort by time (ties: lower original index first)
// denom_i = cumsum(exp(xbeta0[order]))[i]
// cost2   = M(M+1)/2 - sum_ii exp(-xh_ii) * cumsum(exp(xh))[ii]
//
// Sort: time uniform in [0,1000) -> 2^18 value buckets in DESCENDING time
// order; counting sort + per-bucket insertion sort on 50-bit composite key.
//
// GRID=148 blocks x 1024 threads, all co-resident => spin barrier safe.
// Spin uses ld.acquire (no atomic-ALU serialization); arrival is one
// atomicAdd per CTA. g_hist is zero at entry (zeroed at load; re-zeroed in
// the scatter phase each run => invariant across graph replays).
// ---------------------------------------------------------------------------

#define MAXN (1 << 19)
#define NB   (1 << 18)
#define MAXM 16384
#define GRID 148
#define BLK  1024

__device__ unsigned long long g_keys[MAXN];
__device__ int    g_hist[NB];
__device__ int    g_off[NB];
__device__ int    g_off_mut[NB];
__device__ int    g_scanBlk[GRID];
__device__ double g_coxBlk[GRID];
__device__ double g_blockAcc[GRID];
__device__ float  g_xh_glob[MAXM];
__device__ unsigned g_bar_gen = 0;   // monotone across replays (ok)
__device__ unsigned g_bar_cnt = 0;   // returns to 0 after each barrier

__device__ __forceinline__ unsigned ld_acquire(const unsigned* p) {
    unsigned v;
    asm volatile("ld.acquire.gpu.b32 %0, [%1];" : "=r"(v) : "l"(p) : "memory");
    return v;
}

__device__ __forceinline__ void grid_bar() {
    __syncthreads();
    if (threadIdx.x == 0) {
        unsigned gen = ld_acquire(&g_bar_gen);
        __threadfence();                          // release my block's writes
        unsigned arrived = atomicAdd(&g_bar_cnt, 1u);
        if (arrived == GRID - 1) {
            g_bar_cnt = 0;
            __threadfence();
            atomicAdd(&g_bar_gen, 1u);            // release everyone
        } else {
            while (ld_acquire(&g_bar_gen) == gen) __nanosleep(32);
        }
        __threadfence();                          // acquire side
    }
    __syncthreads();
}

__device__ __forceinline__ int bucket_desc(float t) {
    int b = (int)(t * ((float)NB / 1000.0f));
    if (b < 0) b = 0;
    if (b > NB - 1) b = NB - 1;
    return (NB - 1) - b;
}

__global__ __launch_bounds__(BLK, 1)
void fused_kernel(const float* __restrict__ yt0, const float* __restrict__ yp0,
                  const float* __restrict__ yp1, const int* __restrict__ Hj,
                  const float* __restrict__ lv, float* __restrict__ out,
                  int n, int m, int idx_bits, unsigned idx_mask,
                  int CH_N, int CH_B) {
    __shared__ int    sh_i[BLK];
    __shared__ double sh_d[BLK];
    __shared__ float  sh_xh[8192];

    const int b = blockIdx.x, t = threadIdx.x;
    const long baseN = (long)b * CH_N;
    const long baseB = (long)b * CH_B;
    const long endN  = (baseN + CH_N < n)  ? baseN + CH_N : n;
    const long endB  = (baseB + CH_B < NB) ? baseB + CH_B : NB;
    const float2* yt2 = (const float2*)yt0;   // (time, event) pairs

    // ---- P1: histogram (g_hist zero at entry) ----
    for (long i = baseN + t; i < endN; i += BLK)
        atomicAdd(&g_hist[bucket_desc(yt2[i].x)], 1);
    grid_bar();

    // ---- P2: per-block bucket-count sums ----
    {
        int s = 0;
        for (long i = baseB + t; i < endB; i += BLK) s += g_hist[i];
        sh_i[t] = s; __syncthreads();
        for (int off = BLK / 2; off > 0; off >>= 1) {
            if (t < off) sh_i[t] += sh_i[t + off];
            __syncthreads();
        }
        if (t == 0) g_scanBlk[b] = sh_i[0];
    }
    grid_bar();

    // ---- P3: exclusive scan -> bucket offsets ----
    {
        int v = (t < b) ? g_scanBlk[t] : 0;
        sh_i[t] = v; __syncthreads();
        for (int off = BLK / 2; off > 0; off >>= 1) {
            if (t < off) sh_i[t] += sh_i[t + off];
            __syncthreads();
        }
        int base_val = sh_i[0];
        __syncthreads();

        long i0 = baseB + (long)t * 2;
        int l0 = (i0     < endB) ? g_hist[i0]     : 0;
        int l1 = (i0 + 1 < endB) ? g_hist[i0 + 1] : 0;
        int s = l0 + l1;
        sh_i[t] = s; __syncthreads();
        for (int off = 1; off < BLK; off <<= 1) {
            int u = (t >= off) ? sh_i[t - off] : 0;
            __syncthreads();
            sh_i[t] += u;
            __syncthreads();
        }
        int run = base_val + sh_i[t] - s;
        if (i0 < endB)     { g_off[i0] = run;     g_off_mut[i0] = run;     run += l0; }
        if (i0 + 1 < endB) { g_off[i0 + 1] = run; g_off_mut[i0 + 1] = run; }
    }
    grid_bar();

    // ---- P4: scatter keys into bucket slots; re-zero hist chunk ----
    for (long i = baseN + t; i < endN; i += BLK) {
        float2 te = yt2[i];
        unsigned u = __float_as_uint(te.x);
        u = (u & 0x80000000u) ? ~u : (u | 0x80000000u);
        unsigned long long key = ((unsigned long long)u << idx_bits) |
                                 (unsigned long long)(idx_mask - (unsigned)i);
        int bu = bucket_desc(te.x);
        int pos = atomicAdd(&g_off_mut[bu], 1);
        g_keys[pos] = key;
    }
    for (long i = baseB + t; i < endB; i += BLK) g_hist[i] = 0;
    grid_bar();

    // ---- P5: per-bucket insertion sort (descending composite key) ----
    for (long bu = baseB + t; bu < endB; bu += BLK) {
        int s = g_off[bu], e = g_off_mut[bu];
        for (int i = s + 1; i < e; i++) {
            unsigned long long k = g_keys[i];
            int j = i - 1;
            while (j >= s && g_keys[j] < k) { g_keys[j + 1] = g_keys[j]; j--; }
            g_keys[j + 1] = k;
        }
    }
    grid_bar();

    // ---- P6: gather in sorted order (regs) + block exp sum ----
    // mapping: thread t handles elements i0, i0+1 (same mapping reused in P7)
    long i0 = baseN + 2 * (long)t;
    float  xb0 = 0.f, xb1 = 0.f;
    float  ev0 = 0.f, ev1 = 0.f;
    double e0 = 0.0, e1 = 0.0;
    {
        if (i0 < endN) {
            unsigned long long k = g_keys[i0];
            unsigned orig = idx_mask - (unsigned)(k & idx_mask);
            xb0 = yp0[orig];
            ev0 = yt2[orig].y;
            e0 = (double)expf(xb0);
        }
        if (i0 + 1 < endN) {
            unsigned long long k = g_keys[i0 + 1];
            unsigned orig = idx_mask - (unsigned)(k & idx_mask);
            xb1 = yp0[orig];
            ev1 = yt2[orig].y;
            e1 = (double)expf(xb1);
        }
        double s = e0 + e1;
        sh_d[t] = s; __syncthreads();
        for (int off = BLK / 2; off > 0; off >>= 1) {
            if (t < off) sh_d[t] += sh_d[t + off];
            __syncthreads();
        }
        if (t == 0) g_coxBlk[b] = sh_d[0];
    }
    grid_bar();

    // ---- P7: Cox prefix + loss (values still in registers) ----
    {
        double v = (t < b) ? g_coxBlk[t] : 0.0;
        sh_d[t] = v; __syncthreads();
        for (int off = BLK / 2; off > 0; off >>= 1) {
            if (t < off) sh_d[t] += sh_d[t + off];
            __syncthreads();
        }
        double base_val = sh_d[0];
        __syncthreads();

        double s = e0 + e1;
        sh_d[t] = s; __syncthreads();
        for (int off = 1; off < BLK; off <<= 1) {
            double u = (t >= off) ? sh_d[t - off] : 0.0;
            __syncthreads();
            sh_d[t] += u;
            __syncthreads();
        }
        double run = base_val + sh_d[t] - s;
        double acc = 0.0;
        if (i0 < endN) {
            run += e0;
            if (ev0 != 0.0f) acc += (double)logf((float)run) - (double)xb0;
        }
        if (i0 + 1 < endN) {
            run += e1;
            if (ev1 != 0.0f) acc += (double)logf((float)run) - (double)xb1;
        }
        __syncthreads();
        sh_d[t] = acc; __syncthreads();
        for (int off = BLK / 2; off > 0; off >>= 1) {
            if (t < off) sh_d[t] += sh_d[t + off];
            __syncthreads();
        }
        if (t == 0) g_blockAcc[b] = sh_d[0];
    }
    grid_bar();

    // ---- P8: ordinal loss (O(M) prefix identity) + final combine (block 0) ----
    if (b == 0) {
        float* xh = (m <= 8192) ? sh_xh : g_xh_glob;
        int S = (m + BLK - 1) / BLK;
        double tot = 0.0;
        for (int k2 = 0; k2 < S; k2++) {
            int j = t * S + k2;
            if (j < m) {
                int pos = Hj[j];
                unsigned long long key = g_keys[pos];
                unsigned orig = idx_mask - (unsigned)(key & idx_mask);
                float x = yp1[orig];
                xh[j] = x;
                tot += exp((double)x);
            }
        }
        sh_d[t] = tot; __syncthreads();
        for (int off = 1; off < BLK; off <<= 1) {
            double u = (t >= off) ? sh_d[t - off] : 0.0;
            __syncthreads();
            sh_d[t] += u;
            __syncthreads();
        }
        double run = sh_d[t] - tot;
        double acc = 0.0;
        for (int k2 = 0; k2 < S; k2++) {
            int j = t * S + k2;
            if (j < m) {
                double exv = exp((double)xh[j]);
                run += exv;
                acc += run / exv;
            }
        }
        __syncthreads();
        sh_d[t] = acc; __syncthreads();
        for (int off = BLK / 2; off > 0; off >>= 1) {
            if (t < off) sh_d[t] += sh_d[t + off];
            __syncthreads();
        }
        double cost2 = 0.5 * (double)m * ((double)m + 1.0) - sh_d[0];
        __syncthreads();

        double s2 = 0.0;
        for (int k2 = t; k2 < GRID; k2 += BLK) s2 += g_blockAcc[k2];
        sh_d[t] = s2; __syncthreads();
        for (int off = BLK / 2; off > 0; off >>= 1) {
            if (t < off) sh_d[t] += sh_d[t + off];
            __syncthreads();
        }
        if (t == 0) {
            double lv0 = (double)lv[0];
            double lv1 = (double)lv[1];
            double p1 = exp(-lv1);
            if (p1 > 1.0) p1 = 1.0;
            if (p1 < 0.0) p1 = 0.0;
            out[0] = (float)((sh_d[0] + (double)n * lv0) + (p1 * cost2 + lv1));
        }
    }
}

extern "C" void kernel_launch(void* const* d_in, const int* in_sizes, int n_in,
                              void* d_out, int out_size) {
    const float* yt0      = (const float*)d_in[0];   // [N,2] (time, event)
    const float* yp0      = (const float*)d_in[2];   // [N,1] xbeta head 0
    const float* yp1      = (const float*)d_in[3];   // [N,1] xbeta head 1
    const int*   Hj       = (const int*)d_in[4];     // [M]
    const float* log_vars = (const float*)d_in[5];   // [2]

    int n = in_sizes[0] / 2;
    int m = in_sizes[4];

    int idx_bits = 0;
    while ((1u << idx_bits) < (unsigned)n) idx_bits++;
    unsigned idx_mask = (1u << idx_bits) - 1u;

    int CH_N = (n + GRID - 1) / GRID;   // 1772 for N=262144 (<= 2*BLK)
    int CH_B = (NB + GRID - 1) / GRID;

    fused_kernel<<<GRID, BLK>>>(yt0, yp0, yp1, Hj, log_vars, (float*)d_out,
                                n, m, idx_bits, idx_mask, CH_N, CH_B);
}

// round 8
// speedup vs baseline: 1.8508x; 1.8401x over previous
#include <cuda_runtime.h>
#include <math.h>

// ---------------------------------------------------------------------------
// Fully-fused persistent kernel, single launch, lean grid barriers,
// shuffle-based block scans/reductions (minimal serial-cycle count).
//
// loss = sum_i event_i*(log(denom_i) - xbeta0_i) + n*lv0
//      + clip(exp(-lv1),0,1) * cost2 + lv1
// order   = stable descending sort by time (ties: lower original index first)
// denom_i = cumsum(exp(xbeta0[order]))[i]
// cost2   = M(M+1)/2 - sum_ii exp(-xh_ii) * cumsum(exp(xh))[ii]
//
// Sort: time uniform in [0,1000) -> 2^18 value buckets in DESCENDING time
// order; counting sort + per-bucket insertion sort on 50-bit composite key.
//
// GRID<=148 blocks x 256 threads, all co-resident => spin barrier safe.
// g_hist zero at entry (zeroed at load; re-zeroed in scatter phase each run).
// ---------------------------------------------------------------------------

#define MAXN (1 << 19)
#define NB   (1 << 18)
#define MAXM 16384
#define BLK  256
#define EPT  8
#define CH   (BLK * EPT)        // 2048 per block
#define MAXG 148

__device__ unsigned long long g_keys[MAXN];
__device__ int    g_hist[NB];
__device__ int    g_off[NB];
__device__ int    g_off_mut[NB];
__device__ int    g_scanBlk[MAXG];
__device__ double g_coxBlk[MAXG];
__device__ double g_blockAcc[MAXG];
__device__ float  g_xh_glob[MAXM];
__device__ unsigned g_bar_gen = 0;   // monotone across replays (ok)
__device__ unsigned g_bar_cnt = 0;   // returns to 0 after each barrier

__device__ __forceinline__ unsigned ld_acquire(const unsigned* p) {
    unsigned v;
    asm volatile("ld.acquire.gpu.b32 %0, [%1];" : "=r"(v) : "l"(p) : "memory");
    return v;
}

__device__ __forceinline__ void grid_bar(int G) {
    __syncthreads();
    if (threadIdx.x == 0) {
        unsigned gen = ld_acquire(&g_bar_gen);
        __threadfence();                           // release my block's writes
        unsigned arrived = atomicAdd(&g_bar_cnt, 1u);
        if (arrived == (unsigned)(G - 1)) {
            g_bar_cnt = 0;
            __threadfence();
            atomicAdd(&g_bar_gen, 1u);             // release everyone
        } else {
            while (ld_acquire(&g_bar_gen) == gen) { }   // tight poll (L2 read)
        }
        __threadfence();
    }
    __syncthreads();
}

// ---- shuffle-based block primitives (BLK=256 = 8 warps) ----
__device__ __forceinline__ int block_reduce_i(int v, volatile int* sh8, int t) {
    int lane = t & 31;
#pragma unroll
    for (int o = 16; o > 0; o >>= 1) v += __shfl_down_sync(0xffffffffu, v, o);
    if (lane == 0) sh8[t >> 5] = v;
    __syncthreads();
    if (t < 8) {
        int x = sh8[t];
#pragma unroll
        for (int o = 4; o > 0; o >>= 1) x += __shfl_down_sync(0xffu, x, o);
        if (t == 0) sh8[0] = x;
    }
    __syncthreads();
    int r = sh8[0];
    __syncthreads();
    return r;
}

__device__ __forceinline__ double block_reduce_d(double v, volatile double* sh8, int t) {
    int lane = t & 31;
#pragma unroll
    for (int o = 16; o > 0; o >>= 1) v += __shfl_down_sync(0xffffffffu, v, o);
    if (lane == 0) sh8[t >> 5] = v;
    __syncthreads();
    if (t < 8) {
        double x = sh8[t];
#pragma unroll
        for (int o = 4; o > 0; o >>= 1) x += __shfl_down_sync(0xffu, x, o);
        if (t == 0) sh8[0] = x;
    }
    __syncthreads();
    double r = sh8[0];
    __syncthreads();
    return r;
}

__device__ __forceinline__ int block_scan_excl_i(int v, volatile int* sh8, int t) {
    int lane = t & 31, w = t >> 5;
    int x = v;
#pragma unroll
    for (int o = 1; o < 32; o <<= 1) {
        int u = __shfl_up_sync(0xffffffffu, x, o);
        if (lane >= o) x += u;
    }
    if (lane == 31) sh8[w] = x;
    __syncthreads();
    if (t < 8) {
        int y = sh8[t];
#pragma unroll
        for (int o = 1; o < 8; o <<= 1) {
            int u = __shfl_up_sync(0xffu, y, o);
            if (t >= o) y += u;
        }
        sh8[t] = y;
    }
    __syncthreads();
    int r = ((w == 0) ? 0 : sh8[w - 1]) + x - v;
    __syncthreads();
    return r;
}

__device__ __forceinline__ double block_scan_excl_d(double v, volatile double* sh8, int t) {
    int lane = t & 31, w = t >> 5;
    double x = v;
#pragma unroll
    for (int o = 1; o < 32; o <<= 1) {
        double u = __shfl_up_sync(0xffffffffu, x, o);
        if (lane >= o) x += u;
    }
    if (lane == 31) sh8[w] = x;
    __syncthreads();
    if (t < 8) {
        double y = sh8[t];
#pragma unroll
        for (int o = 1; o < 8; o <<= 1) {
            double u = __shfl_up_sync(0xffu, y, o);
            if (t >= o) y += u;
        }
        sh8[t] = y;
    }
    __syncthreads();
    double r = ((w == 0) ? 0.0 : sh8[w - 1]) + x - v;
    __syncthreads();
    return r;
}

__device__ __forceinline__ int bucket_desc(float t) {
    int b = (int)(t * ((float)NB / 1000.0f));
    if (b < 0) b = 0;
    if (b > NB - 1) b = NB - 1;
    return (NB - 1) - b;
}

__global__ __launch_bounds__(BLK, 1)
void fused_kernel(const float* __restrict__ yt0, const float* __restrict__ yp0,
                  const float* __restrict__ yp1, const int* __restrict__ Hj,
                  const float* __restrict__ lv, float* __restrict__ out,
                  int n, int m, int idx_bits, unsigned idx_mask, int G) {
    __shared__ int    sh8i[8];
    __shared__ double sh8d[8];
    __shared__ float  sh_xh[8192];

    const int b = blockIdx.x, t = threadIdx.x;
    const long baseN = (long)b * CH;
    const long baseB = (long)b * CH;
    const long endN  = (baseN + CH < n)  ? baseN + CH : n;
    const long endB  = (baseB + CH < NB) ? baseB + CH : NB;
    const float2* yt2 = (const float2*)yt0;

    // ---- P1: histogram (g_hist zero at entry); coalesced stride-BLK ----
    for (long i = baseN + t; i < endN; i += BLK)
        atomicAdd(&g_hist[bucket_desc(yt2[i].x)], 1);
    grid_bar(G);

    // ---- P2: per-thread contiguous bucket counts (kept in regs) + block sum ----
    const long myB0 = baseB + (long)t * EPT;
    int cnt[EPT];
    int cntSum = 0;
#pragma unroll
    for (int k = 0; k < EPT; k++) {
        long bu = myB0 + k;
        cnt[k] = (bu < endB) ? g_hist[bu] : 0;
        cntSum += cnt[k];
    }
    {
        int tot = block_reduce_i(cntSum, sh8i, t);
        if (t == 0) g_scanBlk[b] = tot;
    }
    grid_bar(G);

    // ---- P3: bucket offsets (base from predecessor blocks + local scan) ----
    {
        int bv = (t < b) ? g_scanBlk[t] : 0;          // G <= 148 < BLK
        int base_val = block_reduce_i(bv, sh8i, t);
        int pref = block_scan_excl_i(cntSum, sh8i, t);
        int run = base_val + pref;
#pragma unroll
        for (int k = 0; k < EPT; k++) {
            long bu = myB0 + k;
            if (bu < endB) { g_off[bu] = run; g_off_mut[bu] = run; run += cnt[k]; }
        }
    }
    grid_bar(G);

    // ---- P4: scatter keys; re-zero hist chunk ----
    for (long i = baseN + t; i < endN; i += BLK) {
        float2 te = yt2[i];
        unsigned u = __float_as_uint(te.x);
        u = (u & 0x80000000u) ? ~u : (u | 0x80000000u);
        unsigned long long key = ((unsigned long long)u << idx_bits) |
                                 (unsigned long long)(idx_mask - (unsigned)i);
        int bu = bucket_desc(te.x);
        int pos = atomicAdd(&g_off_mut[bu], 1);
        g_keys[pos] = key;
    }
    for (long i = baseB + t; i < endB; i += BLK) g_hist[i] = 0;
    grid_bar(G);

    // ---- P5: per-bucket insertion sort (descending composite key) ----
    {
        int offv[EPT + 1];
#pragma unroll
        for (int k = 0; k <= EPT; k++) {
            long bu = myB0 + k;
            offv[k] = (bu < NB) ? g_off[bu] : n;
        }
#pragma unroll
        for (int k = 0; k < EPT; k++) {
            if (myB0 + k < endB) {
                int s = offv[k], e = offv[k + 1];
                for (int i = s + 1; i < e; i++) {
                    unsigned long long kk = g_keys[i];
                    int j = i - 1;
                    while (j >= s && g_keys[j] < kk) { g_keys[j + 1] = g_keys[j]; j--; }
                    g_keys[j + 1] = kk;
                }
            }
        }
    }
    grid_bar(G);

    // ---- P6: gather in sorted order (contiguous EPT run per thread) ----
    const long myN0 = baseN + (long)t * EPT;
    float  xb[EPT], ev[EPT];
    double ex[EPT];
    double exSum = 0.0;
#pragma unroll
    for (int k = 0; k < EPT; k++) {
        long i = myN0 + k;
        if (i < endN) {
            unsigned long long kk = g_keys[i];
            unsigned orig = idx_mask - (unsigned)(kk & idx_mask);
            xb[k] = yp0[orig];
            ev[k] = yt2[orig].y;
            ex[k] = (double)expf(xb[k]);
        } else { xb[k] = 0.f; ev[k] = 0.f; ex[k] = 0.0; }
        exSum += ex[k];
    }
    {
        double tot = block_reduce_d(exSum, sh8d, t);
        if (t == 0) g_coxBlk[b] = tot;
    }
    grid_bar(G);

    // ---- P7: Cox prefix + loss ----
    {
        double bv = (t < b) ? g_coxBlk[t] : 0.0;
        double base_val = block_reduce_d(bv, sh8d, t);
        double pref = block_scan_excl_d(exSum, sh8d, t);
        double run = base_val + pref;
        double acc = 0.0;
#pragma unroll
        for (int k = 0; k < EPT; k++) {
            long i = myN0 + k;
            if (i < endN) {
                run += ex[k];
                if (ev[k] != 0.0f)
                    acc += (double)logf((float)run) - (double)xb[k];
            }
        }
        double tot = block_reduce_d(acc, sh8d, t);
        if (t == 0) g_blockAcc[b] = tot;
    }
    grid_bar(G);

    // ---- P8: ordinal loss (O(M) prefix identity) + final combine (block 0) ----
    if (b == 0) {
        float* xh = (m <= 8192) ? sh_xh : g_xh_glob;
        int S = (m + BLK - 1) / BLK;
        double tot = 0.0;
        for (int k2 = 0; k2 < S; k2++) {
            int j = t * S + k2;
            if (j < m) {
                int pos = Hj[j];
                unsigned long long key = g_keys[pos];
                unsigned orig = idx_mask - (unsigned)(key & idx_mask);
                float x = yp1[orig];
                xh[j] = x;
                tot += (double)expf(x);
            }
        }
        double pref = block_scan_excl_d(tot, sh8d, t);
        double run = pref;
        double acc = 0.0;
        for (int k2 = 0; k2 < S; k2++) {
            int j = t * S + k2;
            if (j < m) {
                float x = xh[j];
                run += (double)expf(x);
                acc += run * (double)expf(-x);
            }
        }
        double sAcc = block_reduce_d(acc, sh8d, t);
        double cost2 = 0.5 * (double)m * ((double)m + 1.0) - sAcc;

        double s2 = 0.0;
        for (int k2 = t; k2 < G; k2 += BLK) s2 += g_blockAcc[k2];
        double coxTot = block_reduce_d(s2, sh8d, t);

        if (t == 0) {
            double lv0 = (double)lv[0];
            double lv1 = (double)lv[1];
            double p1 = exp(-lv1);
            if (p1 > 1.0) p1 = 1.0;
            if (p1 < 0.0) p1 = 0.0;
            out[0] = (float)((coxTot + (double)n * lv0) + (p1 * cost2 + lv1));
        }
    }
}

extern "C" void kernel_launch(void* const* d_in, const int* in_sizes, int n_in,
                              void* d_out, int out_size) {
    const float* yt0      = (const float*)d_in[0];   // [N,2] (time, event)
    const float* yp0      = (const float*)d_in[2];   // [N,1] xbeta head 0
    const float* yp1      = (const float*)d_in[3];   // [N,1] xbeta head 1
    const int*   Hj       = (const int*)d_in[4];     // [M]
    const float* log_vars = (const float*)d_in[5];   // [2]

    int n = in_sizes[0] / 2;
    int m = in_sizes[4];

    int idx_bits = 0;
    while ((1u << idx_bits) < (unsigned)n) idx_bits++;
    unsigned idx_mask = (1u << idx_bits) - 1u;

    int G = (n + CH - 1) / CH;                 // 128 for N=262144
    int GB = (NB + CH - 1) / CH;               // bucket-space blocks
    if (GB > G) G = GB;                        // cover both spaces
    if (G > MAXG) G = MAXG;                    // co-residency cap

    fused_kernel<<<G, BLK>>>(yt0, yp0, yp1, Hj, log_vars, (float*)d_out,
                             n, m, idx_bits, idx_mask, G);
}

// round 9
// speedup vs baseline: 2.3945x; 1.2938x over previous
#include <cuda_runtime.h>
#include <math.h>

// ---------------------------------------------------------------------------
// Fully-fused persistent kernel, single launch, 6 grid barriers,
// shared-memory segment sort, register-resident bucket offsets.
//
// loss = sum_i event_i*(log(denom_i) - xbeta0_i) + n*lv0
//      + clip(exp(-lv1),0,1) * cost2 + lv1
// order   = stable descending sort by time (ties: lower original index first)
// denom_i = cumsum(exp(xbeta0[order]))[i]
// cost2   = M(M+1)/2 - sum_ii exp(-xh_ii) * cumsum(exp(xh))[ii]
//
// Sort: time uniform in [0,1000) -> 2^18 value buckets in DESCENDING time
// order; counting sort + per-bucket insertion sort on 50-bit composite key.
// Each block owns CH=2048 consecutive buckets; its elements are contiguous
// in g_keys => sort the segment in SMEM. Ordinal ranks (Hj) resolved inside
// the sort phase (each block serves ranks falling in its segment).
//
// GRID<=148 x 512, all co-resident => spin barrier safe.
// g_hist zero at entry (zeroed at load; re-zeroed in scatter each run).
// ---------------------------------------------------------------------------

#define MAXN (1 << 19)
#define NB   (1 << 18)
#define MAXM 16384
#define BLK  512
#define NW   (BLK / 32)
#define CH   2048
#define EPT_B (CH / BLK)        // 4 buckets per thread
#define MAXG 148
#define SEGCAP 4352

__device__ unsigned long long g_keys[MAXN];
__device__ int    g_hist[NB];
__device__ int    g_off_mut[NB];
__device__ int    g_scanBlk[MAXG];
__device__ double g_coxBlk[MAXG];
__device__ double g_blockAcc[MAXG];
__device__ float  g_xh[MAXM];
__device__ unsigned g_bar_gen = 0;   // monotone across replays (ok)
__device__ unsigned g_bar_cnt = 0;   // returns to 0 after each barrier

__device__ __forceinline__ unsigned ld_acquire(const unsigned* p) {
    unsigned v;
    asm volatile("ld.acquire.gpu.b32 %0, [%1];" : "=r"(v) : "l"(p) : "memory");
    return v;
}

__device__ __forceinline__ void grid_bar(int G) {
    __syncthreads();
    if (threadIdx.x == 0) {
        unsigned gen = ld_acquire(&g_bar_gen);
        __threadfence();
        unsigned arrived = atomicAdd(&g_bar_cnt, 1u);
        if (arrived == (unsigned)(G - 1)) {
            g_bar_cnt = 0;
            __threadfence();
            atomicAdd(&g_bar_gen, 1u);
        } else {
            while (ld_acquire(&g_bar_gen) == gen) { }
        }
        __threadfence();
    }
    __syncthreads();
}

// ---- shuffle block primitives (BLK = 512 = 16 warps) ----
__device__ __forceinline__ int block_reduce_i(int v, volatile int* shw, int t) {
    int lane = t & 31;
#pragma unroll
    for (int o = 16; o > 0; o >>= 1) v += __shfl_down_sync(0xffffffffu, v, o);
    if (lane == 0) shw[t >> 5] = v;
    __syncthreads();
    if (t < NW) {
        int x = shw[t];
#pragma unroll
        for (int o = NW / 2; o > 0; o >>= 1) x += __shfl_down_sync((1u << NW) - 1u, x, o);
        if (t == 0) shw[0] = x;
    }
    __syncthreads();
    int r = shw[0];
    __syncthreads();
    return r;
}

__device__ __forceinline__ double block_reduce_d(double v, volatile double* shw, int t) {
    int lane = t & 31;
#pragma unroll
    for (int o = 16; o > 0; o >>= 1) v += __shfl_down_sync(0xffffffffu, v, o);
    if (lane == 0) shw[t >> 5] = v;
    __syncthreads();
    if (t < NW) {
        double x = shw[t];
#pragma unroll
        for (int o = NW / 2; o > 0; o >>= 1) x += __shfl_down_sync((1u << NW) - 1u, x, o);
        if (t == 0) shw[0] = x;
    }
    __syncthreads();
    double r = shw[0];
    __syncthreads();
    return r;
}

__device__ __forceinline__ int block_scan_excl_i(int v, volatile int* shw, int t) {
    int lane = t & 31, w = t >> 5;
    int x = v;
#pragma unroll
    for (int o = 1; o < 32; o <<= 1) {
        int u = __shfl_up_sync(0xffffffffu, x, o);
        if (lane >= o) x += u;
    }
    if (lane == 31) shw[w] = x;
    __syncthreads();
    if (t < NW) {
        int y = shw[t];
#pragma unroll
        for (int o = 1; o < NW; o <<= 1) {
            int u = __shfl_up_sync((1u << NW) - 1u, y, o);
            if (t >= o) y += u;
        }
        shw[t] = y;
    }
    __syncthreads();
    int r = ((w == 0) ? 0 : shw[w - 1]) + x - v;
    __syncthreads();
    return r;
}

__device__ __forceinline__ double block_scan_excl_d(double v, volatile double* shw, int t) {
    int lane = t & 31, w = t >> 5;
    double x = v;
#pragma unroll
    for (int o = 1; o < 32; o <<= 1) {
        double u = __shfl_up_sync(0xffffffffu, x, o);
        if (lane >= o) x += u;
    }
    if (lane == 31) shw[w] = x;
    __syncthreads();
    if (t < NW) {
        double y = shw[t];
#pragma unroll
        for (int o = 1; o < NW; o <<= 1) {
            double u = __shfl_up_sync((1u << NW) - 1u, y, o);
            if (t >= o) y += u;
        }
        shw[t] = y;
    }
    __syncthreads();
    double r = ((w == 0) ? 0.0 : shw[w - 1]) + x - v;
    __syncthreads();
    return r;
}

__device__ __forceinline__ int bucket_desc(float t) {
    int b = (int)(t * ((float)NB / 1000.0f));
    if (b < 0) b = 0;
    if (b > NB - 1) b = NB - 1;
    return (NB - 1) - b;
}

__global__ __launch_bounds__(BLK, 1)
void fused_kernel(const float* __restrict__ yt0, const float* __restrict__ yp0,
                  const float* __restrict__ yp1, const int* __restrict__ Hj,
                  const float* __restrict__ lv, float* __restrict__ out,
                  int n, int m, int idx_bits, unsigned idx_mask, int G) {
    __shared__ unsigned long long s_keys[SEGCAP];
    __shared__ int    shw_i[NW];
    __shared__ double shw_d[NW];

    const int b = blockIdx.x, t = threadIdx.x;
    const long baseN = (long)b * CH;
    const long endN  = (baseN + CH < n) ? baseN + CH : n;
    const long baseB = (long)b * CH;
    const long endB  = (baseB + CH < NB) ? baseB + CH : NB;
    const float2* yt2 = (const float2*)yt0;

    // ---- P1: histogram (g_hist zero at entry) ----
    for (long i = baseN + t; i < endN; i += BLK)
        atomicAdd(&g_hist[bucket_desc(yt2[i].x)], 1);
    grid_bar(G);

    // ---- P2: per-thread bucket counts (regs) + block total ----
    const long myB0 = baseB + (long)t * EPT_B;
    int cnt[EPT_B];
    int cntSum = 0;
#pragma unroll
    for (int k = 0; k < EPT_B; k++) {
        long bu = myB0 + k;
        cnt[k] = (bu < endB) ? g_hist[bu] : 0;
        cntSum += cnt[k];
    }
    int ownTot = block_reduce_i(cntSum, shw_i, t);
    if (t == 0) g_scanBlk[b] = ownTot;
    grid_bar(G);

    // ---- P3: segment start + per-thread bucket offsets (kept in regs) ----
    int bv = (t < b) ? g_scanBlk[t] : 0;             // G <= BLK
    const int segStart = block_reduce_i(bv, shw_i, t);
    int pref_i = block_scan_excl_i(cntSum, shw_i, t);
    int off0[EPT_B];
    {
        int run = segStart + pref_i;
#pragma unroll
        for (int k = 0; k < EPT_B; k++) {
            off0[k] = run;
            long bu = myB0 + k;
            if (bu < endB) g_off_mut[bu] = run;
            run += cnt[k];
        }
    }
    grid_bar(G);

    // ---- P4: scatter keys; re-zero hist chunk ----
    for (long i = baseN + t; i < endN; i += BLK) {
        float2 te = yt2[i];
        unsigned u = __float_as_uint(te.x);
        u = (u & 0x80000000u) ? ~u : (u | 0x80000000u);
        unsigned long long key = ((unsigned long long)u << idx_bits) |
                                 (unsigned long long)(idx_mask - (unsigned)i);
        int bu = bucket_desc(te.x);
        int pos = atomicAdd(&g_off_mut[bu], 1);
        g_keys[pos] = key;
    }
    for (long i = baseB + t; i < endB; i += BLK) g_hist[i] = 0;
    grid_bar(G);

    // ---- P5: sort own segment in SMEM; serve Hj ranks; exp pass A ----
    const int seg = ownTot;
    const bool useSmem = (seg <= SEGCAP);
    unsigned long long* kb;           // indexed by GLOBAL element index
    if (useSmem) {
        for (int i = t; i < seg; i += BLK) s_keys[i] = g_keys[segStart + i];
        kb = s_keys - segStart;
    } else {
        kb = g_keys;
    }
    __syncthreads();

    // per-bucket insertion sort (descending composite key) on own buckets
#pragma unroll
    for (int k = 0; k < EPT_B; k++) {
        int s = off0[k], e = s + cnt[k];
        for (int i = s + 1; i < e; i++) {
            unsigned long long kk = kb[i];
            int j = i - 1;
            while (j >= s && kb[j] < kk) { kb[j + 1] = kb[j]; j--; }
            kb[j + 1] = kk;
        }
    }
    __syncthreads();

    // serve ordinal ranks landing in my segment: g_xh[j] = yp1[orig(rank Hj[j])]
    {
        int HPT = (m + BLK - 1) / BLK;
        int segEnd = segStart + seg;
        for (int k2 = 0; k2 < HPT; k2++) {
            int j = t * HPT + k2;
            if (j < m) {
                int r = Hj[j];
                if (r >= segStart && r < segEnd) {
                    unsigned long long kk = kb[r];
                    unsigned orig = idx_mask - (unsigned)(kk & idx_mask);
                    g_xh[j] = yp1[orig];
                }
            }
        }
    }

    // pass A: per-thread exp sums over own (contiguous) elements
    double exSum = 0.0;
    {
        int s = off0[0];
        for (int i2 = 0; i2 < cntSum; i2++) {
            unsigned long long kk = kb[s + i2];
            unsigned orig = idx_mask - (unsigned)(kk & idx_mask);
            exSum += (double)expf(yp0[orig]);
        }
    }
    double pref_d = block_scan_excl_d(exSum, shw_d, t);
    {
        double tot = block_reduce_d(exSum, shw_d, t);
        if (t == 0) g_coxBlk[b] = tot;
    }
    grid_bar(G);

    // ---- P6: Cox prefix + loss (pass B over own elements) ----
    {
        double bv2 = (t < b) ? g_coxBlk[t] : 0.0;
        double base_val = block_reduce_d(bv2, shw_d, t);
        double run = base_val + pref_d;
        double acc = 0.0;
        int s = off0[0];
        for (int i2 = 0; i2 < cntSum; i2++) {
            unsigned long long kk = kb[s + i2];
            unsigned orig = idx_mask - (unsigned)(kk & idx_mask);
            float xbv = yp0[orig];
            float evv = yt2[orig].y;
            run += (double)expf(xbv);
            if (evv != 0.0f)
                acc += (double)logf((float)run) - (double)xbv;
        }
        double tot = block_reduce_d(acc, shw_d, t);
        if (t == 0) g_blockAcc[b] = tot;
    }
    grid_bar(G);

    // ---- P7: ordinal scan (O(M)) + final combine (block 0) ----
    if (b == 0) {
        int S = (m + BLK - 1) / BLK;
        double tot = 0.0;
        for (int k2 = 0; k2 < S; k2++) {
            int j = t * S + k2;
            if (j < m) tot += (double)expf(g_xh[j]);
        }
        double pref2 = block_scan_excl_d(tot, shw_d, t);
        double run2 = pref2;
        double acc2 = 0.0;
        for (int k2 = 0; k2 < S; k2++) {
            int j = t * S + k2;
            if (j < m) {
                float x = g_xh[j];
                run2 += (double)expf(x);
                acc2 += run2 * (double)expf(-x);
            }
        }
        double sAcc = block_reduce_d(acc2, shw_d, t);
        double cost2 = 0.5 * (double)m * ((double)m + 1.0) - sAcc;

        double s2 = 0.0;
        for (int k2 = t; k2 < G; k2 += BLK) s2 += g_blockAcc[k2];
        double coxTot = block_reduce_d(s2, shw_d, t);

        if (t == 0) {
            double lv0 = (double)lv[0];
            double lv1 = (double)lv[1];
            double p1 = exp(-lv1);
            if (p1 > 1.0) p1 = 1.0;
            if (p1 < 0.0) p1 = 0.0;
            out[0] = (float)((coxTot + (double)n * lv0) + (p1 * cost2 + lv1));
        }
    }
}

extern "C" void kernel_launch(void* const* d_in, const int* in_sizes, int n_in,
                              void* d_out, int out_size) {
    const float* yt0      = (const float*)d_in[0];   // [N,2] (time, event)
    const float* yp0      = (const float*)d_in[2];   // [N,1] xbeta head 0
    const float* yp1      = (const float*)d_in[3];   // [N,1] xbeta head 1
    const int*   Hj       = (const int*)d_in[4];     // [M]
    const float* log_vars = (const float*)d_in[5];   // [2]

    int n = in_sizes[0] / 2;
    int m = in_sizes[4];

    int idx_bits = 0;
    while ((1u << idx_bits) < (unsigned)n) idx_bits++;
    unsigned idx_mask = (1u << idx_bits) - 1u;

    int G  = (n + CH - 1) / CH;               // 128 for N=262144
    int GB = (NB + CH - 1) / CH;              // 128
    if (GB > G) G = GB;
    if (G > MAXG) G = MAXG;

    fused_kernel<<<G, BLK>>>(yt0, yp0, yp1, Hj, log_vars, (float*)d_out,
                             n, m, idx_bits, idx_mask, G);
}